// round 1
// baseline (speedup 1.0000x reference)
#include <cuda_runtime.h>
#include <cuda_bf16.h>
#include <mma.h>
#include <math.h>

using namespace nvcuda;

// ---------------- problem constants ----------------
#define BB 8
#define TT 2048
#define DD 1024
#define NN 32768
#define KSEL 64
#define HH 16
#define DH 64
#define LN_EPS 1e-5f

#define BT (BB*TT)          // 16384
#define BTD (BB*TT*DD)      // 16777216
#define DD2 (DD*DD)         // 1048576

// ---------------- device scratch (no allocs allowed) ----------------
__device__ __nv_bfloat16 g_hnorm[BTD];          // 33.5 MB
__device__ float g_mu[BT];
__device__ float g_rstd[BT];
__device__ float g_hsumraw[BB*DD];
__device__ float g_fq[BB*DD];
__device__ float g_sel[BB*NN];
__device__ int   g_topk[BB*KSEL];
__device__ __nv_bfloat16 g_tkmem[BB*KSEL*DD];
__device__ float g_k[BB*KSEL*DD];
__device__ float g_v[BB*KSEL*DD];
__device__ float g_q[BTD];                      // 67 MB
__device__ __nv_bfloat16 g_attnout[BTD];        // 33.5 MB
__device__ float g_o[BTD];                      // 67 MB
__device__ float g_attnsum[BB*KSEL];
__device__ __nv_bfloat16 g_wbf[4*DD2];          // qw, kw, vw, ow in bf16

// ---------------- zero small accumulators ----------------
__global__ void zero_kernel() {
    int i = blockIdx.x*256 + threadIdx.x;
    if (i < BB*DD) g_hsumraw[i] = 0.f;
    if (i < BB*KSEL) g_attnsum[i] = 0.f;
}

// ---------------- LayerNorm: per-row mean/var, write bf16 h_norm ----------------
__global__ __launch_bounds__(256) void ln_kernel(const float* __restrict__ h,
                                                 const float* __restrict__ lg,
                                                 const float* __restrict__ lb) {
    int row = blockIdx.x;
    int tid = threadIdx.x;
    const float4* x4 = (const float4*)(h + (size_t)row*DD);
    float4 v = x4[tid];
    float s  = v.x + v.y + v.z + v.w;
    float s2 = v.x*v.x + v.y*v.y + v.z*v.z + v.w*v.w;
    #pragma unroll
    for (int o = 16; o; o >>= 1) {
        s  += __shfl_xor_sync(0xffffffffu, s, o);
        s2 += __shfl_xor_sync(0xffffffffu, s2, o);
    }
    __shared__ float ws[8], ws2[8];
    __shared__ float smu, srstd;
    if ((tid & 31) == 0) { ws[tid>>5] = s; ws2[tid>>5] = s2; }
    __syncthreads();
    if (tid == 0) {
        float ts = 0.f, ts2 = 0.f;
        #pragma unroll
        for (int i = 0; i < 8; i++) { ts += ws[i]; ts2 += ws2[i]; }
        float mu = ts / DD;
        float var = ts2 / DD - mu*mu;
        float rstd = rsqrtf(var + LN_EPS);
        smu = mu; srstd = rstd;
        g_mu[row] = mu; g_rstd[row] = rstd;
    }
    __syncthreads();
    float mu = smu, rstd = srstd;
    const float4* g4 = (const float4*)lg;
    const float4* b4 = (const float4*)lb;
    float4 gg = g4[tid], bb = b4[tid];
    __nv_bfloat16* out = g_hnorm + (size_t)row*DD + tid*4;
    out[0] = __float2bfloat16((v.x - mu)*rstd*gg.x + bb.x);
    out[1] = __float2bfloat16((v.y - mu)*rstd*gg.y + bb.y);
    out[2] = __float2bfloat16((v.z - mu)*rstd*gg.z + bb.z);
    out[3] = __float2bfloat16((v.w - mu)*rstd*gg.w + bb.w);
}

// ---------------- column sums of h_norm (fp32 precision path) ----------------
// h_summary[b][j] = mean_t((h-mu)*rstd)*g[j] + b[j]; raw sum accumulated here.
__global__ __launch_bounds__(256) void hsum_kernel(const float* __restrict__ h) {
    int b = blockIdx.x;        // 0..7
    int jc = blockIdx.y;       // 0..3
    int tc = blockIdx.z;       // 0..7
    int j = jc*256 + threadIdx.x;
    float acc = 0.f;
    int t0 = tc*256;
    for (int t = t0; t < t0 + 256; t++) {
        int r = b*TT + t;
        acc += (h[(size_t)r*DD + j] - g_mu[r]) * g_rstd[r];
    }
    atomicAdd(&g_hsumraw[b*DD + j], acc);
}

// ---------------- focus_query = h_summary @ focus_w + focus_b (fp32) ----------------
__global__ __launch_bounds__(256) void focus_kernel(const float* __restrict__ fw,
                                                    const float* __restrict__ fb,
                                                    const float* __restrict__ lg,
                                                    const float* __restrict__ lb) {
    int b = blockIdx.x;
    int tid = threadIdx.x;
    __shared__ float hs[DD];
    for (int i = tid; i < DD; i += 256)
        hs[i] = (g_hsumraw[b*DD + i] * (1.f/TT)) * lg[i] + lb[i];
    __syncthreads();
    float acc[4] = {0.f, 0.f, 0.f, 0.f};
    for (int i = 0; i < DD; i++) {
        float hv = hs[i];
        const float* fr = fw + (size_t)i*DD + tid;
        acc[0] += hv * fr[0];
        acc[1] += hv * fr[256];
        acc[2] += hv * fr[512];
        acc[3] += hv * fr[768];
    }
    #pragma unroll
    for (int k = 0; k < 4; k++)
        g_fq[b*DD + tid + k*256] = acc[k] + fb[tid + k*256];
}

// ---------------- selection = fq @ memory^T + aw * activations ----------------
__global__ __launch_bounds__(256) void sel_kernel(const float* __restrict__ mem,
                                                  const float* __restrict__ act,
                                                  const float* __restrict__ awp) {
    __shared__ float fqs[BB][DD];   // 32 KB
    int tid = threadIdx.x;
    for (int i = tid; i < BB*DD; i += 256)
        fqs[i >> 10][i & 1023] = g_fq[i];
    __syncthreads();
    int warp = tid >> 5, lane = tid & 31;
    int n = blockIdx.x*8 + warp;
    float acc[BB];
    #pragma unroll
    for (int b = 0; b < BB; b++) acc[b] = 0.f;
    const float* mrow = mem + (size_t)n*DD;
    for (int i = lane; i < DD; i += 32) {
        float m = mrow[i];
        #pragma unroll
        for (int b = 0; b < BB; b++) acc[b] += m * fqs[b][i];
    }
    #pragma unroll
    for (int b = 0; b < BB; b++) {
        float a = acc[b];
        #pragma unroll
        for (int o = 16; o; o >>= 1) a += __shfl_xor_sync(0xffffffffu, a, o);
        if (lane == 0) g_sel[b*NN + n] = a + awp[0] * act[b*NN + n];
    }
}

// ---------------- top-64 per batch via iterative argmax ----------------
__global__ __launch_bounds__(1024) void topk_kernel() {
    int b = blockIdx.x;
    int tid = threadIdx.x;
    __shared__ float wv[32];
    __shared__ int   wi[32];
    float* sel = g_sel + b*NN;
    for (int iter = 0; iter < KSEL; iter++) {
        float v = -INFINITY; int id = NN;
        for (int i = tid; i < NN; i += 1024) {
            float s = sel[i];
            if (s > v || (s == v && i < id)) { v = s; id = i; }
        }
        #pragma unroll
        for (int o = 16; o; o >>= 1) {
            float ov = __shfl_xor_sync(0xffffffffu, v, o);
            int   oi = __shfl_xor_sync(0xffffffffu, id, o);
            if (ov > v || (ov == v && oi < id)) { v = ov; id = oi; }
        }
        if ((tid & 31) == 0) { wv[tid>>5] = v; wi[tid>>5] = id; }
        __syncthreads();
        if (tid == 0) {
            float bv = wv[0]; int bi = wi[0];
            for (int i = 1; i < 32; i++) {
                if (wv[i] > bv || (wv[i] == bv && wi[i] < bi)) { bv = wv[i]; bi = wi[i]; }
            }
            g_topk[b*KSEL + iter] = bi;
            sel[bi] = -INFINITY;
        }
        __syncthreads();
    }
}

// ---------------- gather top-k memory rows -> bf16 ----------------
__global__ __launch_bounds__(256) void gather_kernel(const float* __restrict__ mem) {
    int bk = blockIdx.x;                 // 0..511
    int idx = g_topk[bk];
    const float* src = mem + (size_t)idx*DD;
    __nv_bfloat16* dst = g_tkmem + (size_t)bk*DD;
    for (int i = threadIdx.x; i < DD; i += 256)
        dst[i] = __float2bfloat16(src[i]);
}

// ---------------- convert weights to bf16 ----------------
__global__ void convw_kernel(const float* __restrict__ qw, const float* __restrict__ kw,
                             const float* __restrict__ vw, const float* __restrict__ ow) {
    for (int i = blockIdx.x*256 + threadIdx.x; i < DD2; i += gridDim.x*256) {
        g_wbf[i]         = __float2bfloat16(qw[i]);
        g_wbf[DD2 + i]   = __float2bfloat16(kw[i]);
        g_wbf[2*DD2 + i] = __float2bfloat16(vw[i]);
        g_wbf[3*DD2 + i] = __float2bfloat16(ow[i]);
    }
}

// ---------------- bf16 WMMA GEMM: C = A(MxK) @ B(KxN) + bias ----------------
#define GBM 128
#define GBN 128
#define GBK 32
__global__ __launch_bounds__(256) void gemm_bf16(const __nv_bfloat16* __restrict__ A,
                                                 const __nv_bfloat16* __restrict__ Bm,
                                                 const float* __restrict__ bias,
                                                 float* __restrict__ C,
                                                 int M, int N, int K) {
    __shared__ __align__(16) __nv_bfloat16 As[GBM][GBK];
    __shared__ __align__(16) __nv_bfloat16 Bs[GBK][GBN];
    __shared__ __align__(16) float biasT[16][GBN];
    int tid = threadIdx.x;
    int warp = tid >> 5;
    int wm = warp >> 1;          // 0..3 (32 rows each)
    int wn = warp & 1;           // 0..1 (64 cols each)
    int rowBase = blockIdx.y * GBM;
    int colBase = blockIdx.x * GBN;

    for (int i = tid; i < 16*GBN; i += 256)
        biasT[i >> 7][i & 127] = bias[colBase + (i & 127)];
    __syncthreads();

    wmma::fragment<wmma::accumulator, 16, 16, 16, float> acc[2][4];
    #pragma unroll
    for (int i = 0; i < 2; i++)
        #pragma unroll
        for (int j = 0; j < 4; j++)
            wmma::load_matrix_sync(acc[i][j], &biasT[0][wn*64 + j*16], GBN, wmma::mem_row_major);
    __syncthreads();

    for (int k0 = 0; k0 < K; k0 += GBK) {
        #pragma unroll
        for (int r = 0; r < 2; r++) {
            int idx = tid + r*256;
            int arow = idx >> 2;  int ac = (idx & 3) * 8;
            *(uint4*)&As[arow][ac] = *(const uint4*)&A[(size_t)(rowBase + arow)*K + k0 + ac];
            int brow = idx >> 4;  int bc = (idx & 15) * 8;
            *(uint4*)&Bs[brow][bc] = *(const uint4*)&Bm[(size_t)(k0 + brow)*N + colBase + bc];
        }
        __syncthreads();
        #pragma unroll
        for (int kk = 0; kk < GBK; kk += 16) {
            wmma::fragment<wmma::matrix_a, 16, 16, 16, __nv_bfloat16, wmma::row_major> af[2];
            wmma::fragment<wmma::matrix_b, 16, 16, 16, __nv_bfloat16, wmma::row_major> bf[4];
            #pragma unroll
            for (int i = 0; i < 2; i++)
                wmma::load_matrix_sync(af[i], &As[wm*32 + i*16][kk], GBK);
            #pragma unroll
            for (int j = 0; j < 4; j++)
                wmma::load_matrix_sync(bf[j], &Bs[kk][wn*64 + j*16], GBN);
            #pragma unroll
            for (int i = 0; i < 2; i++)
                #pragma unroll
                for (int j = 0; j < 4; j++)
                    wmma::mma_sync(acc[i][j], af[i], bf[j], acc[i][j]);
        }
        __syncthreads();
    }
    #pragma unroll
    for (int i = 0; i < 2; i++)
        #pragma unroll
        for (int j = 0; j < 4; j++)
            wmma::store_matrix_sync(&C[(size_t)(rowBase + wm*32 + i*16)*N + colBase + wn*64 + j*16],
                                    acc[i][j], N, wmma::mem_row_major);
}

// ---------------- small-K cross-attention ----------------
// grid (B*H, T/128), block 128. One thread = one t.
__global__ __launch_bounds__(128) void attn_kernel() {
    int bh = blockIdx.x;
    int b = bh >> 4;
    int h = bh & 15;
    int tid = threadIdx.x;
    int t = blockIdx.y*128 + tid;

    __shared__ __align__(16) float Ks[KSEL][DH];
    __shared__ __align__(16) float Vs[KSEL][DH];
    __shared__ float aacc[KSEL];

    if (tid < KSEL) aacc[tid] = 0.f;
    for (int i = tid; i < KSEL*DH; i += 128) {
        int kk = i >> 6, dh = i & 63;
        int gi = ((b*KSEL) + kk)*DD + h*DH + dh;
        Ks[kk][dh] = g_k[gi];
        Vs[kk][dh] = g_v[gi];
    }
    __syncthreads();

    const float4* qp = (const float4*)(g_q + (size_t)(b*TT + t)*DD + h*DH);
    float4 q[16];
    #pragma unroll
    for (int i = 0; i < 16; i++) q[i] = qp[i];

    float o[DH];
    #pragma unroll
    for (int d = 0; d < DH; d++) o[d] = 0.f;
    float l = 0.f;

    // pass 1: unnormalized softmax + value accumulation (scores bounded, no max needed)
    for (int kk = 0; kk < KSEL; kk++) {
        const float4* kr = (const float4*)Ks[kk];
        float s = 0.f;
        #pragma unroll
        for (int i = 0; i < 16; i++) {
            float4 kv = kr[i];
            s += q[i].x*kv.x + q[i].y*kv.y + q[i].z*kv.z + q[i].w*kv.w;
        }
        float p = __expf(s * 0.125f);
        l += p;
        const float4* vr = (const float4*)Vs[kk];
        #pragma unroll
        for (int i = 0; i < 16; i++) {
            float4 vv = vr[i];
            o[4*i+0] += p*vv.x; o[4*i+1] += p*vv.y; o[4*i+2] += p*vv.z; o[4*i+3] += p*vv.w;
        }
    }
    float inv = 1.f / l;
    __nv_bfloat16* op = g_attnout + (size_t)(b*TT + t)*DD + h*DH;
    #pragma unroll
    for (int d = 0; d < DH; d++) op[d] = __float2bfloat16(o[d]*inv);

    // pass 2: recompute p for attn-mean accumulation
    for (int kk = 0; kk < KSEL; kk++) {
        const float4* kr = (const float4*)Ks[kk];
        float s = 0.f;
        #pragma unroll
        for (int i = 0; i < 16; i++) {
            float4 kv = kr[i];
            s += q[i].x*kv.x + q[i].y*kv.y + q[i].z*kv.z + q[i].w*kv.w;
        }
        float p = __expf(s * 0.125f) * inv;
        #pragma unroll
        for (int off = 16; off; off >>= 1) p += __shfl_xor_sync(0xffffffffu, p, off);
        if ((tid & 31) == 0) atomicAdd(&aacc[kk], p);
    }
    __syncthreads();
    if (tid < KSEL) atomicAdd(&g_attnsum[b*KSEL + tid], aacc[tid]);
}

// ---------------- epilogue: h_updated = h + gate * (attnout@ow + ob) ----------------
__global__ __launch_bounds__(256) void final_kernel(const float* __restrict__ h,
                                                    const float* __restrict__ glp,
                                                    float* __restrict__ dout) {
    int i = blockIdx.x*256 + threadIdx.x;        // over float4 elements
    float gate = 1.f / (1.f + __expf(-glp[0]));
    const float4* h4 = (const float4*)h;
    const float4* o4 = (const float4*)g_o;
    float4* d4 = (float4*)dout;
    float4 hv = h4[i], ov = o4[i];
    float4 r;
    r.x = hv.x + gate*ov.x; r.y = hv.y + gate*ov.y;
    r.z = hv.z + gate*ov.z; r.w = hv.w + gate*ov.w;
    d4[i] = r;
}

// ---------------- full_attn: zero then scatter mean attention ----------------
__global__ void zerofa_kernel(float* __restrict__ dout) {
    int i = blockIdx.x*256 + threadIdx.x;
    if (i < BB*NN) dout[BTD + i] = 0.f;
}
__global__ void scatter_kernel(float* __restrict__ dout) {
    int i = threadIdx.x;                 // 0..511
    if (i < BB*KSEL) {
        int b = i >> 6;
        dout[BTD + b*NN + g_topk[i]] = g_attnsum[i] * (1.f / (HH*TT));
    }
}

// ---------------- launch ----------------
extern "C" void kernel_launch(void* const* d_in, const int* in_sizes, int n_in,
                              void* d_out, int out_size) {
    const float* h    = (const float*)d_in[0];
    const float* mem  = (const float*)d_in[1];
    const float* act  = (const float*)d_in[2];
    const float* ln_g = (const float*)d_in[3];
    const float* ln_b = (const float*)d_in[4];
    const float* fw   = (const float*)d_in[5];
    const float* fb   = (const float*)d_in[6];
    const float* qw   = (const float*)d_in[7];
    const float* qb   = (const float*)d_in[8];
    const float* kw   = (const float*)d_in[9];
    const float* kb   = (const float*)d_in[10];
    const float* vw   = (const float*)d_in[11];
    const float* vb   = (const float*)d_in[12];
    const float* ow   = (const float*)d_in[13];
    const float* ob   = (const float*)d_in[14];
    const float* awp  = (const float*)d_in[15];
    const float* glp  = (const float*)d_in[16];
    float* dout = (float*)d_out;

    __nv_bfloat16 *wq, *wk, *wv, *wo;
    cudaGetSymbolAddress((void**)&wq, g_wbf);
    wk = wq + DD2; wv = wq + 2*DD2; wo = wq + 3*DD2;
    __nv_bfloat16 *hnorm, *tkmem, *attnout;
    cudaGetSymbolAddress((void**)&hnorm, g_hnorm);
    cudaGetSymbolAddress((void**)&tkmem, g_tkmem);
    cudaGetSymbolAddress((void**)&attnout, g_attnout);
    float *dq, *dk, *dv, *dov;
    cudaGetSymbolAddress((void**)&dq, g_q);
    cudaGetSymbolAddress((void**)&dk, g_k);
    cudaGetSymbolAddress((void**)&dv, g_v);
    cudaGetSymbolAddress((void**)&dov, g_o);

    zero_kernel<<<34, 256>>>();
    convw_kernel<<<2048, 256>>>(qw, kw, vw, ow);
    ln_kernel<<<BT, 256>>>(h, ln_g, ln_b);
    hsum_kernel<<<dim3(BB, 4, 8), 256>>>(h);
    focus_kernel<<<BB, 256>>>(fw, fb, ln_g, ln_b);
    sel_kernel<<<NN/8, 256>>>(mem, act, awp);
    topk_kernel<<<BB, 1024>>>();
    gather_kernel<<<BB*KSEL, 256>>>(mem);

    gemm_bf16<<<dim3(DD/GBN, BT/GBM), 256>>>(hnorm, wq, qb, dq, BT, DD, DD);
    gemm_bf16<<<dim3(DD/GBN, (BB*KSEL)/GBM), 256>>>(tkmem, wk, kb, dk, BB*KSEL, DD, DD);
    gemm_bf16<<<dim3(DD/GBN, (BB*KSEL)/GBM), 256>>>(tkmem, wv, vb, dv, BB*KSEL, DD, DD);

    attn_kernel<<<dim3(BB*HH, TT/128), 128>>>();

    gemm_bf16<<<dim3(DD/GBN, BT/GBM), 256>>>(attnout, wo, ob, dov, BT, DD, DD);

    final_kernel<<<(BTD/4 + 255)/256, 256>>>(h, glp, dout);
    zerofa_kernel<<<(BB*NN + 255)/256, 256>>>(dout);
    scatter_kernel<<<1, 512>>>(dout);
}

// round 2
// speedup vs baseline: 2.2419x; 2.2419x over previous
#include <cuda_runtime.h>
#include <cuda_bf16.h>
#include <mma.h>
#include <math.h>

using namespace nvcuda;

// ---------------- problem constants ----------------
#define BB 8
#define TT 2048
#define DD 1024
#define NN 32768
#define KSEL 64
#define HH 16
#define DH 64
#define LN_EPS 1e-5f

#define BT (BB*TT)          // 16384
#define BTD (BB*TT*DD)      // 16777216
#define DD2 (DD*DD)         // 1048576

// ---------------- device scratch ----------------
__device__ __nv_bfloat16 g_hnorm[BTD];
__device__ float g_mu[BT];
__device__ float g_rstd[BT];
__device__ float g_hsumraw[BB*DD];
__device__ float g_fq[BB*DD];
__device__ float g_sel[BB*NN];
__device__ int   g_topk[BB*KSEL];
__device__ __nv_bfloat16 g_tkmem[BB*KSEL*DD];
__device__ float g_kv[2*BB*KSEL*DD];            // k then v
__device__ float g_q[BTD];
__device__ __nv_bfloat16 g_attnout[BTD];
__device__ float g_attnsum[BB*KSEL];
__device__ __nv_bfloat16 g_wbf[4*DD2];          // qw, kw, vw, ow bf16

// ---------------- zero accumulators + full_attn region of dout ----------------
__global__ void zero_kernel(float* __restrict__ dout) {
    int i = blockIdx.x*256 + threadIdx.x;
    if (i < BB*DD) { g_hsumraw[i] = 0.f; g_fq[i] = 0.f; }
    if (i < BB*KSEL) g_attnsum[i] = 0.f;
    if (i < BB*NN) dout[BTD + i] = 0.f;
}

// ---------------- LayerNorm -> bf16 h_norm ----------------
__global__ __launch_bounds__(256) void ln_kernel(const float* __restrict__ h,
                                                 const float* __restrict__ lg,
                                                 const float* __restrict__ lb) {
    int row = blockIdx.x;
    int tid = threadIdx.x;
    const float4* x4 = (const float4*)(h + (size_t)row*DD);
    float4 v = x4[tid];
    float s  = v.x + v.y + v.z + v.w;
    float s2 = v.x*v.x + v.y*v.y + v.z*v.z + v.w*v.w;
    #pragma unroll
    for (int o = 16; o; o >>= 1) {
        s  += __shfl_xor_sync(0xffffffffu, s, o);
        s2 += __shfl_xor_sync(0xffffffffu, s2, o);
    }
    __shared__ float ws[8], ws2[8];
    __shared__ float smu, srstd;
    if ((tid & 31) == 0) { ws[tid>>5] = s; ws2[tid>>5] = s2; }
    __syncthreads();
    if (tid == 0) {
        float ts = 0.f, ts2 = 0.f;
        #pragma unroll
        for (int i = 0; i < 8; i++) { ts += ws[i]; ts2 += ws2[i]; }
        float mu = ts / DD;
        float var = ts2 / DD - mu*mu;
        float rstd = rsqrtf(var + LN_EPS);
        smu = mu; srstd = rstd;
        g_mu[row] = mu; g_rstd[row] = rstd;
    }
    __syncthreads();
    float mu = smu, rstd = srstd;
    const float4* g4 = (const float4*)lg;
    const float4* b4 = (const float4*)lb;
    float4 gg = g4[tid], bb = b4[tid];
    __nv_bfloat16* out = g_hnorm + (size_t)row*DD + tid*4;
    out[0] = __float2bfloat16((v.x - mu)*rstd*gg.x + bb.x);
    out[1] = __float2bfloat16((v.y - mu)*rstd*gg.y + bb.y);
    out[2] = __float2bfloat16((v.z - mu)*rstd*gg.z + bb.z);
    out[3] = __float2bfloat16((v.w - mu)*rstd*gg.w + bb.w);
}

// ---------------- column sums of normalized h (fp32 path), 4-way MLP ----------------
__global__ __launch_bounds__(256) void hsum_kernel(const float* __restrict__ h) {
    int b = blockIdx.x;
    int j = blockIdx.y*256 + threadIdx.x;
    int t0 = blockIdx.z*128;
    float a0=0.f, a1=0.f, a2=0.f, a3=0.f;
    for (int t = t0; t < t0 + 128; t += 4) {
        int r = b*TT + t;
        a0 += (h[(size_t)r*DD + j]     - g_mu[r])   * g_rstd[r];
        a1 += (h[(size_t)(r+1)*DD + j] - g_mu[r+1]) * g_rstd[r+1];
        a2 += (h[(size_t)(r+2)*DD + j] - g_mu[r+2]) * g_rstd[r+2];
        a3 += (h[(size_t)(r+3)*DD + j] - g_mu[r+3]) * g_rstd[r+3];
    }
    atomicAdd(&g_hsumraw[b*DD + j], (a0+a1)+(a2+a3));
}

// ---------------- focus_query (fp32), split over K-slices ----------------
__global__ __launch_bounds__(256) void focus_kernel(const float* __restrict__ fw,
                                                    const float* __restrict__ fb,
                                                    const float* __restrict__ lg,
                                                    const float* __restrict__ lb) {
    int b = blockIdx.x;
    int z = blockIdx.y;            // 0..7 k-slices of 128
    int tid = threadIdx.x;
    __shared__ float hs[128];
    for (int i = tid; i < 128; i += 256) {
        int gi = z*128 + i;
        hs[i] = (g_hsumraw[b*DD + gi] * (1.f/TT)) * lg[gi] + lb[gi];
    }
    __syncthreads();
    float acc[4] = {0.f, 0.f, 0.f, 0.f};
    for (int i = 0; i < 128; i++) {
        float hv = hs[i];
        const float* fr = fw + (size_t)(z*128 + i)*DD + tid;
        acc[0] += hv * fr[0];
        acc[1] += hv * fr[256];
        acc[2] += hv * fr[512];
        acc[3] += hv * fr[768];
    }
    #pragma unroll
    for (int k = 0; k < 4; k++) {
        float v = acc[k];
        if (z == 0) v += fb[tid + k*256];
        atomicAdd(&g_fq[b*DD + tid + k*256], v);
    }
}

// ---------------- selection = fq @ memory^T + aw * activations ----------------
__global__ __launch_bounds__(256) void sel_kernel(const float* __restrict__ mem,
                                                  const float* __restrict__ act,
                                                  const float* __restrict__ awp) {
    __shared__ float fqs[BB][DD];
    int tid = threadIdx.x;
    for (int i = tid; i < BB*DD; i += 256)
        fqs[i >> 10][i & 1023] = g_fq[i];
    __syncthreads();
    int warp = tid >> 5, lane = tid & 31;
    int n = blockIdx.x*8 + warp;
    float acc[BB];
    #pragma unroll
    for (int b = 0; b < BB; b++) acc[b] = 0.f;
    const float* mrow = mem + (size_t)n*DD;
    for (int i = lane; i < DD; i += 32) {
        float m = mrow[i];
        #pragma unroll
        for (int b = 0; b < BB; b++) acc[b] += m * fqs[b][i];
    }
    #pragma unroll
    for (int b = 0; b < BB; b++) {
        float a = acc[b];
        #pragma unroll
        for (int o = 16; o; o >>= 1) a += __shfl_xor_sync(0xffffffffu, a, o);
        if (lane == 0) g_sel[b*NN + n] = a + awp[0] * act[b*NN + n];
    }
}

// ---------------- exact top-64 via MSB-first radix select ----------------
__device__ __forceinline__ unsigned fkey(float f) {
    unsigned u = __float_as_uint(f);
    return (u & 0x80000000u) ? ~u : (u | 0x80000000u);
}

__global__ __launch_bounds__(1024) void topk_kernel() {
    int b = blockIdx.x;
    int tid = threadIdx.x;
    __shared__ unsigned hist[256];
    __shared__ unsigned s_prefix;
    __shared__ int s_remaining;
    __shared__ unsigned s_gt, s_eq;
    __shared__ int eqidx[256];
    const float* sel = g_sel + b*NN;
    unsigned prefix = 0;
    int remaining = KSEL;
    for (int shift = 24; shift >= 0; shift -= 8) {
        if (tid < 256) hist[tid] = 0;
        __syncthreads();
        for (int i = tid; i < NN; i += 1024) {
            unsigned k = fkey(sel[i]);
            bool match = (shift == 24) || ((k >> (shift+8)) == (prefix >> (shift+8)));
            if (match) atomicAdd(&hist[(k >> shift) & 255], 1u);
        }
        __syncthreads();
        if (tid == 0) {
            int cum = 0; int j = 255;
            for (; j > 0; j--) {
                if (cum + (int)hist[j] >= remaining) break;
                cum += hist[j];
            }
            s_prefix = prefix | ((unsigned)j << shift);
            s_remaining = remaining - cum;
        }
        __syncthreads();
        prefix = s_prefix;
        remaining = s_remaining;
        __syncthreads();
    }
    if (tid == 0) { s_gt = 0; s_eq = 0; }
    __syncthreads();
    int* out = g_topk + b*KSEL;
    for (int i = tid; i < NN; i += 1024) {
        unsigned k = fkey(sel[i]);
        if (k > prefix) {
            out[atomicAdd(&s_gt, 1u)] = i;
        } else if (k == prefix) {
            unsigned p = atomicAdd(&s_eq, 1u);
            if (p < 256) eqidx[p] = i;
        }
    }
    __syncthreads();
    if (tid == 0) {
        int cnt = min((int)s_eq, 256);
        int base = (int)s_gt;
        for (int r = 0; r < remaining; r++) {
            int mi = 0;
            for (int i2 = 1; i2 < cnt; i2++)
                if (eqidx[i2] < eqidx[mi]) mi = i2;
            out[base + r] = eqidx[mi];
            eqidx[mi] = 0x7fffffff;
        }
    }
}

// ---------------- gather top-k memory rows -> bf16 ----------------
__global__ __launch_bounds__(256) void gather_kernel(const float* __restrict__ mem) {
    int bk = blockIdx.x;
    int idx = g_topk[bk];
    const float* src = mem + (size_t)idx*DD;
    __nv_bfloat16* dst = g_tkmem + (size_t)bk*DD;
    for (int i = threadIdx.x; i < DD; i += 256)
        dst[i] = __float2bfloat16(src[i]);
}

// ---------------- convert weights to bf16 ----------------
__global__ void convw_kernel(const float* __restrict__ qw, const float* __restrict__ kw,
                             const float* __restrict__ vw, const float* __restrict__ ow) {
    for (int i = blockIdx.x*256 + threadIdx.x; i < DD2; i += gridDim.x*256) {
        g_wbf[i]         = __float2bfloat16(qw[i]);
        g_wbf[DD2 + i]   = __float2bfloat16(kw[i]);
        g_wbf[2*DD2 + i] = __float2bfloat16(vw[i]);
        g_wbf[3*DD2 + i] = __float2bfloat16(ow[i]);
    }
}

// ---------------- 3-stage cp.async pipelined bf16 WMMA GEMM ----------------
// EPI 0: C = A@B + bias (float out)
// EPI 1: dout = h + gate*(A@B + bias)         (residual-fused o-proj)
// EPI 2: blockIdx.z picks (B + z*DD2, bias/bias2, C + z*slab)  (fused k/v)
#define STG 3
#define BMG 128
#define BNG 128
#define BKG 64
#define ALD (BKG+8)    // 72 bf16 = 144B rows
#define BLD (BNG+8)    // 136 bf16 = 272B rows
#define SMEM_GEMM (STG*(BMG*ALD + BKG*BLD)*2 + 16*BNG*4)

template<int EPI>
__global__ __launch_bounds__(256) void gemm_bf16(
    const __nv_bfloat16* __restrict__ A,
    const __nv_bfloat16* __restrict__ Bm,
    const float* __restrict__ bias,
    const float* __restrict__ bias2,
    float* __restrict__ C,
    const float* __restrict__ hres,
    const float* __restrict__ glp,
    int M, int N, int K)
{
    extern __shared__ char smraw[];
    __nv_bfloat16* As = (__nv_bfloat16*)smraw;
    __nv_bfloat16* Bs = As + STG*BMG*ALD;
    float* biasT = (float*)(Bs + STG*BKG*BLD);

    int tid = threadIdx.x;
    int warp = tid >> 5;
    int wm = warp >> 2;          // 0..1 -> 64 rows
    int wn = warp & 3;           // 0..3 -> 32 cols
    int rowBase = blockIdx.y * BMG;
    int colBase = blockIdx.x * BNG;

    const __nv_bfloat16* Bp = Bm;
    float* Cp = C;
    const float* bp = bias;
    if (EPI == 2) {
        int z = blockIdx.z;
        Bp = Bm + (size_t)z * DD2;
        Cp = C + (size_t)z * (BB*KSEL*DD);
        bp = z ? bias2 : bias;
    }

    for (int i = tid; i < 16*BNG; i += 256)
        biasT[i] = bp[colBase + (i & (BNG-1))];
    __syncthreads();

    wmma::fragment<wmma::accumulator,16,16,16,float> acc[4][2];
    #pragma unroll
    for (int mi = 0; mi < 4; mi++)
        #pragma unroll
        for (int ni = 0; ni < 2; ni++)
            wmma::load_matrix_sync(acc[mi][ni], biasT + wn*32 + ni*16, BNG, wmma::mem_row_major);

    auto load_stage = [&](int s, int k0) {
        #pragma unroll
        for (int c = 0; c < 4; c++) {
            int lin = tid + c*256;
            int ar = lin >> 3, ac = (lin & 7)*8;
            unsigned da = (unsigned)__cvta_generic_to_shared(As + s*BMG*ALD + ar*ALD + ac);
            const void* ga = A + (size_t)(rowBase+ar)*K + k0 + ac;
            asm volatile("cp.async.cg.shared.global [%0], [%1], 16;\n" :: "r"(da), "l"(ga));
            int br = lin >> 4, bc = (lin & 15)*8;
            unsigned db = (unsigned)__cvta_generic_to_shared(Bs + s*BKG*BLD + br*BLD + bc);
            const void* gb = Bp + (size_t)(k0+br)*N + colBase + bc;
            asm volatile("cp.async.cg.shared.global [%0], [%1], 16;\n" :: "r"(db), "l"(gb));
        }
        asm volatile("cp.async.commit_group;\n");
    };

    int NK = K / BKG;
    load_stage(0, 0);
    load_stage(1, BKG);

    for (int i = 0; i < NK; i++) {
        asm volatile("cp.async.wait_group %0;\n" :: "n"(STG-2));
        __syncthreads();
        if (i + STG - 1 < NK) load_stage((i + STG - 1) % STG, (i + STG - 1) * BKG);
        else asm volatile("cp.async.commit_group;\n");
        int buf = i % STG;
        const __nv_bfloat16* Ab = As + buf*BMG*ALD + wm*64*ALD;
        const __nv_bfloat16* Bb = Bs + buf*BKG*BLD + wn*32;
        #pragma unroll
        for (int kk = 0; kk < BKG; kk += 16) {
            wmma::fragment<wmma::matrix_a,16,16,16,__nv_bfloat16,wmma::row_major> af[4];
            wmma::fragment<wmma::matrix_b,16,16,16,__nv_bfloat16,wmma::row_major> bf[2];
            #pragma unroll
            for (int mi = 0; mi < 4; mi++)
                wmma::load_matrix_sync(af[mi], Ab + mi*16*ALD + kk, ALD);
            #pragma unroll
            for (int ni = 0; ni < 2; ni++)
                wmma::load_matrix_sync(bf[ni], Bb + kk*BLD + ni*16, BLD);
            #pragma unroll
            for (int mi = 0; mi < 4; mi++)
                #pragma unroll
                for (int ni = 0; ni < 2; ni++)
                    wmma::mma_sync(acc[mi][ni], af[mi], bf[ni], acc[mi][ni]);
        }
    }

    if (EPI == 1) {
        asm volatile("cp.async.wait_group 0;\n");
        __syncthreads();
        float* Cs = (float*)smraw;   // 128 x 132
        #pragma unroll
        for (int mi = 0; mi < 4; mi++)
            #pragma unroll
            for (int ni = 0; ni < 2; ni++)
                wmma::store_matrix_sync(Cs + (wm*64 + mi*16)*132 + wn*32 + ni*16,
                                        acc[mi][ni], 132, wmma::mem_row_major);
        __syncthreads();
        float gate = 1.f / (1.f + __expf(-glp[0]));
        for (int c = tid; c < BMG*(BNG/4); c += 256) {
            int r = c >> 5, c4 = (c & 31)*4;
            size_t gi = (size_t)(rowBase + r)*N + colBase + c4;
            float4 hv = *(const float4*)(hres + gi);
            float4 cv = *(float4*)(Cs + r*132 + c4);
            float4 o;
            o.x = hv.x + gate*cv.x; o.y = hv.y + gate*cv.y;
            o.z = hv.z + gate*cv.z; o.w = hv.w + gate*cv.w;
            *(float4*)(C + gi) = o;
        }
    } else {
        #pragma unroll
        for (int mi = 0; mi < 4; mi++)
            #pragma unroll
            for (int ni = 0; ni < 2; ni++)
                wmma::store_matrix_sync(Cp + (size_t)(rowBase + wm*64 + mi*16)*N + colBase + wn*32 + ni*16,
                                        acc[mi][ni], N, wmma::mem_row_major);
    }
}

// ---------------- small-K cross-attention, 256 t per block, no recompute ----------------
#define PSLD 69
#define SMEM_ATTN ((64*64 + 64*64 + 256*PSLD + 256 + 64)*4)
__global__ __launch_bounds__(256) void attn_kernel() {
    extern __shared__ float sm[];
    float* Ks   = sm;                    // [64][64]
    float* Vs   = Ks + 64*64;            // [64][64]
    float* Ps   = Vs + 64*64;            // [256][PSLD]
    float* invs = Ps + 256*PSLD;         // [256]
    float* aacc = invs + 256;            // [64]

    int bh = blockIdx.x;
    int b = bh >> 4;
    int h = bh & 15;
    int tid = threadIdx.x;
    int t = blockIdx.y*256 + tid;

    if (tid < KSEL) aacc[tid] = 0.f;
    const float* kbase = g_kv + (size_t)b*KSEL*DD + h*DH;
    const float* vbase = kbase + (size_t)BB*KSEL*DD;
    for (int i = tid; i < KSEL*DH/4; i += 256) {
        int kk = i >> 4, dh4 = (i & 15)*4;
        *(float4*)&Ks[kk*64 + dh4] = *(const float4*)&kbase[(size_t)kk*DD + dh4];
        *(float4*)&Vs[kk*64 + dh4] = *(const float4*)&vbase[(size_t)kk*DD + dh4];
    }
    __syncthreads();

    const float4* qp = (const float4*)(g_q + (size_t)(b*TT + t)*DD + h*DH);
    float4 q[16];
    #pragma unroll
    for (int i = 0; i < 16; i++) q[i] = qp[i];

    // pass 1: scores -> unnormalized p in smem, accumulate l
    float l = 0.f;
    float* prow = Ps + tid*PSLD;
    for (int kk = 0; kk < KSEL; kk++) {
        const float4* kr = (const float4*)(Ks + kk*64);
        float s = 0.f;
        #pragma unroll
        for (int i = 0; i < 16; i++) {
            float4 kv = kr[i];
            s += q[i].x*kv.x + q[i].y*kv.y + q[i].z*kv.z + q[i].w*kv.w;
        }
        float p = __expf(s * 0.125f);
        l += p;
        prow[kk] = p;
    }
    float inv = 1.f / l;
    invs[tid] = inv;

    // pass 2: out accumulation from stashed p
    float o[DH];
    #pragma unroll
    for (int d = 0; d < DH; d++) o[d] = 0.f;
    for (int kk = 0; kk < KSEL; kk++) {
        float p = prow[kk];
        const float4* vr = (const float4*)(Vs + kk*64);
        #pragma unroll
        for (int i = 0; i < 16; i++) {
            float4 vv = vr[i];
            o[4*i+0] += p*vv.x; o[4*i+1] += p*vv.y;
            o[4*i+2] += p*vv.z; o[4*i+3] += p*vv.w;
        }
    }
    __nv_bfloat16* op = g_attnout + (size_t)(b*TT + t)*DD + h*DH;
    #pragma unroll
    for (int d = 0; d < DH; d++) op[d] = __float2bfloat16(o[d]*inv);

    __syncthreads();
    // column reduce for mean attention: thread -> (kk = tid&63, t-segment = tid>>6)
    {
        int kk = tid & 63;
        int seg = tid >> 6;
        float part = 0.f;
        for (int tt = seg*64; tt < seg*64 + 64; tt++)
            part += Ps[tt*PSLD + kk] * invs[tt];
        atomicAdd(&aacc[kk], part);
    }
    __syncthreads();
    if (tid < KSEL) atomicAdd(&g_attnsum[b*KSEL + tid], aacc[tid]);
}

// ---------------- scatter mean attention ----------------
__global__ void scatter_kernel(float* __restrict__ dout) {
    int i = threadIdx.x;
    if (i < BB*KSEL) {
        int b = i >> 6;
        dout[BTD + b*NN + g_topk[i]] = g_attnsum[i] * (1.f / (HH*TT));
    }
}

// ---------------- launch ----------------
extern "C" void kernel_launch(void* const* d_in, const int* in_sizes, int n_in,
                              void* d_out, int out_size) {
    const float* h    = (const float*)d_in[0];
    const float* mem  = (const float*)d_in[1];
    const float* act  = (const float*)d_in[2];
    const float* ln_g = (const float*)d_in[3];
    const float* ln_b = (const float*)d_in[4];
    const float* fw   = (const float*)d_in[5];
    const float* fb   = (const float*)d_in[6];
    const float* qw   = (const float*)d_in[7];
    const float* qb   = (const float*)d_in[8];
    const float* kw   = (const float*)d_in[9];
    const float* kb   = (const float*)d_in[10];
    const float* vw   = (const float*)d_in[11];
    const float* vb   = (const float*)d_in[12];
    const float* ow   = (const float*)d_in[13];
    const float* ob   = (const float*)d_in[14];
    const float* awp  = (const float*)d_in[15];
    const float* glp  = (const float*)d_in[16];
    float* dout = (float*)d_out;

    __nv_bfloat16 *wq;
    cudaGetSymbolAddress((void**)&wq, g_wbf);
    __nv_bfloat16 *wk = wq + DD2, *wo = wq + 3*DD2;
    __nv_bfloat16 *hnorm, *tkmem, *attnout;
    cudaGetSymbolAddress((void**)&hnorm, g_hnorm);
    cudaGetSymbolAddress((void**)&tkmem, g_tkmem);
    cudaGetSymbolAddress((void**)&attnout, g_attnout);
    float *dq, *dkv;
    cudaGetSymbolAddress((void**)&dq, g_q);
    cudaGetSymbolAddress((void**)&dkv, g_kv);

    cudaFuncSetAttribute(gemm_bf16<0>, cudaFuncAttributeMaxDynamicSharedMemorySize, SMEM_GEMM);
    cudaFuncSetAttribute(gemm_bf16<1>, cudaFuncAttributeMaxDynamicSharedMemorySize, SMEM_GEMM);
    cudaFuncSetAttribute(gemm_bf16<2>, cudaFuncAttributeMaxDynamicSharedMemorySize, SMEM_GEMM);
    cudaFuncSetAttribute(attn_kernel, cudaFuncAttributeMaxDynamicSharedMemorySize, SMEM_ATTN);

    zero_kernel<<<(BB*NN + 255)/256, 256>>>(dout);
    convw_kernel<<<2048, 256>>>(qw, kw, vw, ow);
    ln_kernel<<<BT, 256>>>(h, ln_g, ln_b);
    hsum_kernel<<<dim3(BB, 4, 16), 256>>>(h);
    focus_kernel<<<dim3(BB, 8), 256>>>(fw, fb, ln_g, ln_b);
    sel_kernel<<<NN/8, 256>>>(mem, act, awp);
    topk_kernel<<<BB, 1024>>>();
    gather_kernel<<<BB*KSEL, 256>>>(mem);

    gemm_bf16<0><<<dim3(DD/BNG, BT/BMG), 256, SMEM_GEMM>>>(
        hnorm, wq, qb, nullptr, dq, nullptr, nullptr, BT, DD, DD);
    gemm_bf16<2><<<dim3(DD/BNG, (BB*KSEL)/BMG, 2), 256, SMEM_GEMM>>>(
        tkmem, wk, kb, vb, dkv, nullptr, nullptr, BB*KSEL, DD, DD);

    attn_kernel<<<dim3(BB*HH, TT/256), 256, SMEM_ATTN>>>();

    gemm_bf16<1><<<dim3(DD/BNG, BT/BMG), 256, SMEM_GEMM>>>(
        attnout, wo, ob, nullptr, dout, h, glp, BT, DD, DD);

    scatter_kernel<<<1, 512>>>(dout);
}

// round 3
// speedup vs baseline: 3.4786x; 1.5516x over previous
#include <cuda_runtime.h>
#include <cuda_bf16.h>
#include <mma.h>
#include <math.h>

using namespace nvcuda;

// ---------------- problem constants ----------------
#define BB 8
#define TT 2048
#define DD 1024
#define NN 32768
#define KSEL 64
#define HH 16
#define DH 64
#define LN_EPS 1e-5f

#define BT (BB*TT)          // 16384
#define BTD (BB*TT*DD)      // 16777216
#define DD2 (DD*DD)         // 1048576

// ---------------- device scratch ----------------
__device__ __nv_bfloat16 g_hnorm[BTD];
__device__ float g_mu[BT];
__device__ float g_rstd[BT];
__device__ float g_hsumraw[BB*DD];
__device__ float g_fq[BB*DD];
__device__ float g_sel[BB*NN];
__device__ int   g_topk[BB*KSEL];
__device__ __nv_bfloat16 g_tkmem[BB*KSEL*DD];
__device__ __nv_bfloat16 g_kvbf[2*BB*KSEL*DD];  // k then v (bf16)
__device__ __nv_bfloat16 g_qbf[BTD];            // q bf16
__device__ __nv_bfloat16 g_attnout[BTD];
__device__ float g_attnsum[BB*KSEL];
__device__ __nv_bfloat16 g_wbf[4*DD2];          // qw, kw, vw, ow bf16

// ---------------- zero accumulators + full_attn region of dout ----------------
__global__ void zero_kernel(float* __restrict__ dout) {
    int i = blockIdx.x*256 + threadIdx.x;
    if (i < BB*DD) { g_hsumraw[i] = 0.f; g_fq[i] = 0.f; }
    if (i < BB*KSEL) g_attnsum[i] = 0.f;
    if (i < BB*NN) dout[BTD + i] = 0.f;
}

// ---------------- LayerNorm -> bf16 h_norm ----------------
__global__ __launch_bounds__(256) void ln_kernel(const float* __restrict__ h,
                                                 const float* __restrict__ lg,
                                                 const float* __restrict__ lb) {
    int row = blockIdx.x;
    int tid = threadIdx.x;
    const float4* x4 = (const float4*)(h + (size_t)row*DD);
    float4 v = x4[tid];
    float s  = v.x + v.y + v.z + v.w;
    float s2 = v.x*v.x + v.y*v.y + v.z*v.z + v.w*v.w;
    #pragma unroll
    for (int o = 16; o; o >>= 1) {
        s  += __shfl_xor_sync(0xffffffffu, s, o);
        s2 += __shfl_xor_sync(0xffffffffu, s2, o);
    }
    __shared__ float ws[8], ws2[8];
    __shared__ float smu, srstd;
    if ((tid & 31) == 0) { ws[tid>>5] = s; ws2[tid>>5] = s2; }
    __syncthreads();
    if (tid == 0) {
        float ts = 0.f, ts2 = 0.f;
        #pragma unroll
        for (int i = 0; i < 8; i++) { ts += ws[i]; ts2 += ws2[i]; }
        float mu = ts / DD;
        float var = ts2 / DD - mu*mu;
        float rstd = rsqrtf(var + LN_EPS);
        smu = mu; srstd = rstd;
        g_mu[row] = mu; g_rstd[row] = rstd;
    }
    __syncthreads();
    float mu = smu, rstd = srstd;
    const float4* g4 = (const float4*)lg;
    const float4* b4 = (const float4*)lb;
    float4 gg = g4[tid], bb = b4[tid];
    __nv_bfloat16* out = g_hnorm + (size_t)row*DD + tid*4;
    out[0] = __float2bfloat16((v.x - mu)*rstd*gg.x + bb.x);
    out[1] = __float2bfloat16((v.y - mu)*rstd*gg.y + bb.y);
    out[2] = __float2bfloat16((v.z - mu)*rstd*gg.z + bb.z);
    out[3] = __float2bfloat16((v.w - mu)*rstd*gg.w + bb.w);
}

// ---------------- column sums of normalized h (fp32 path), 4-way MLP ----------------
__global__ __launch_bounds__(256) void hsum_kernel(const float* __restrict__ h) {
    int b = blockIdx.x;
    int j = blockIdx.y*256 + threadIdx.x;
    int t0 = blockIdx.z*128;
    float a0=0.f, a1=0.f, a2=0.f, a3=0.f;
    for (int t = t0; t < t0 + 128; t += 4) {
        int r = b*TT + t;
        a0 += (h[(size_t)r*DD + j]     - g_mu[r])   * g_rstd[r];
        a1 += (h[(size_t)(r+1)*DD + j] - g_mu[r+1]) * g_rstd[r+1];
        a2 += (h[(size_t)(r+2)*DD + j] - g_mu[r+2]) * g_rstd[r+2];
        a3 += (h[(size_t)(r+3)*DD + j] - g_mu[r+3]) * g_rstd[r+3];
    }
    atomicAdd(&g_hsumraw[b*DD + j], (a0+a1)+(a2+a3));
}

// ---------------- focus_query (fp32), split over K-slices ----------------
__global__ __launch_bounds__(256) void focus_kernel(const float* __restrict__ fw,
                                                    const float* __restrict__ fb,
                                                    const float* __restrict__ lg,
                                                    const float* __restrict__ lb) {
    int b = blockIdx.x;
    int z = blockIdx.y;
    int tid = threadIdx.x;
    __shared__ float hs[128];
    for (int i = tid; i < 128; i += 256) {
        int gi = z*128 + i;
        hs[i] = (g_hsumraw[b*DD + gi] * (1.f/TT)) * lg[gi] + lb[gi];
    }
    __syncthreads();
    float acc[4] = {0.f, 0.f, 0.f, 0.f};
    for (int i = 0; i < 128; i++) {
        float hv = hs[i];
        const float* fr = fw + (size_t)(z*128 + i)*DD + tid;
        acc[0] += hv * fr[0];
        acc[1] += hv * fr[256];
        acc[2] += hv * fr[512];
        acc[3] += hv * fr[768];
    }
    #pragma unroll
    for (int k = 0; k < 4; k++) {
        float v = acc[k];
        if (z == 0) v += fb[tid + k*256];
        atomicAdd(&g_fq[b*DD + tid + k*256], v);
    }
}

// ---------------- selection = fq @ memory^T + aw * activations ----------------
__global__ __launch_bounds__(256) void sel_kernel(const float* __restrict__ mem,
                                                  const float* __restrict__ act,
                                                  const float* __restrict__ awp) {
    __shared__ float fqs[BB][DD];
    int tid = threadIdx.x;
    for (int i = tid; i < BB*DD; i += 256)
        fqs[i >> 10][i & 1023] = g_fq[i];
    __syncthreads();
    int warp = tid >> 5, lane = tid & 31;
    int n = blockIdx.x*8 + warp;
    float acc[BB];
    #pragma unroll
    for (int b = 0; b < BB; b++) acc[b] = 0.f;
    const float* mrow = mem + (size_t)n*DD;
    for (int i = lane; i < DD; i += 32) {
        float m = mrow[i];
        #pragma unroll
        for (int b = 0; b < BB; b++) acc[b] += m * fqs[b][i];
    }
    #pragma unroll
    for (int b = 0; b < BB; b++) {
        float a = acc[b];
        #pragma unroll
        for (int o = 16; o; o >>= 1) a += __shfl_xor_sync(0xffffffffu, a, o);
        if (lane == 0) g_sel[b*NN + n] = a + awp[0] * act[b*NN + n];
    }
}

// ---------------- exact top-64 via MSB-first radix select ----------------
__device__ __forceinline__ unsigned fkey(float f) {
    unsigned u = __float_as_uint(f);
    return (u & 0x80000000u) ? ~u : (u | 0x80000000u);
}

__global__ __launch_bounds__(1024) void topk_kernel() {
    int b = blockIdx.x;
    int tid = threadIdx.x;
    __shared__ unsigned hist[256];
    __shared__ unsigned s_prefix;
    __shared__ int s_remaining;
    __shared__ unsigned s_gt, s_eq;
    __shared__ int eqidx[256];
    const float* sel = g_sel + b*NN;
    unsigned prefix = 0;
    int remaining = KSEL;
    for (int shift = 24; shift >= 0; shift -= 8) {
        if (tid < 256) hist[tid] = 0;
        __syncthreads();
        for (int i = tid; i < NN; i += 1024) {
            unsigned k = fkey(sel[i]);
            bool match = (shift == 24) || ((k >> (shift+8)) == (prefix >> (shift+8)));
            if (match) atomicAdd(&hist[(k >> shift) & 255], 1u);
        }
        __syncthreads();
        if (tid == 0) {
            int cum = 0; int j = 255;
            for (; j > 0; j--) {
                if (cum + (int)hist[j] >= remaining) break;
                cum += hist[j];
            }
            s_prefix = prefix | ((unsigned)j << shift);
            s_remaining = remaining - cum;
        }
        __syncthreads();
        prefix = s_prefix;
        remaining = s_remaining;
        __syncthreads();
    }
    if (tid == 0) { s_gt = 0; s_eq = 0; }
    __syncthreads();
    int* out = g_topk + b*KSEL;
    for (int i = tid; i < NN; i += 1024) {
        unsigned k = fkey(sel[i]);
        if (k > prefix) {
            out[atomicAdd(&s_gt, 1u)] = i;
        } else if (k == prefix) {
            unsigned p = atomicAdd(&s_eq, 1u);
            if (p < 256) eqidx[p] = i;
        }
    }
    __syncthreads();
    if (tid == 0) {
        int cnt = min((int)s_eq, 256);
        int base = (int)s_gt;
        for (int r = 0; r < remaining; r++) {
            int mi = 0;
            for (int i2 = 1; i2 < cnt; i2++)
                if (eqidx[i2] < eqidx[mi]) mi = i2;
            out[base + r] = eqidx[mi];
            eqidx[mi] = 0x7fffffff;
        }
    }
}

// ---------------- gather top-k memory rows -> bf16 ----------------
__global__ __launch_bounds__(256) void gather_kernel(const float* __restrict__ mem) {
    int bk = blockIdx.x;
    int idx = g_topk[bk];
    const float* src = mem + (size_t)idx*DD;
    __nv_bfloat16* dst = g_tkmem + (size_t)bk*DD;
    for (int i = threadIdx.x; i < DD; i += 256)
        dst[i] = __float2bfloat16(src[i]);
}

// ---------------- convert weights to bf16 ----------------
__global__ void convw_kernel(const float* __restrict__ qw, const float* __restrict__ kw,
                             const float* __restrict__ vw, const float* __restrict__ ow) {
    for (int i = blockIdx.x*256 + threadIdx.x; i < DD2; i += gridDim.x*256) {
        g_wbf[i]         = __float2bfloat16(qw[i]);
        g_wbf[DD2 + i]   = __float2bfloat16(kw[i]);
        g_wbf[2*DD2 + i] = __float2bfloat16(vw[i]);
        g_wbf[3*DD2 + i] = __float2bfloat16(ow[i]);
    }
}

// ---------------- 3-stage cp.async pipelined bf16 WMMA GEMM ----------------
// EPI 0: bf16 out = A@B + bias  (q)
// EPI 1: fp32 out = h + gate*(A@B + bias)   (residual-fused o-proj)
// EPI 2: bf16 out, blockIdx.z picks weight/bias/dest slab (fused k/v)
#define STG 3
#define BMG 128
#define BNG 128
#define BKG 64
#define ALD (BKG+8)
#define BLD (BNG+8)
#define SMEM_GEMM (STG*(BMG*ALD + BKG*BLD)*2 + 16*BNG*4)

template<int EPI>
__global__ __launch_bounds__(256, 2) void gemm_bf16(
    const __nv_bfloat16* __restrict__ A,
    const __nv_bfloat16* __restrict__ Bm,
    const float* __restrict__ bias,
    const float* __restrict__ bias2,
    void* __restrict__ Cout,
    const float* __restrict__ hres,
    const float* __restrict__ glp,
    int M, int N, int K)
{
    extern __shared__ char smraw[];
    __nv_bfloat16* As = (__nv_bfloat16*)smraw;
    __nv_bfloat16* Bs = As + STG*BMG*ALD;
    float* biasT = (float*)(Bs + STG*BKG*BLD);

    int tid = threadIdx.x;
    int warp = tid >> 5;
    int wm = warp >> 2;          // 0..1 -> 64 rows
    int wn = warp & 3;           // 0..3 -> 32 cols
    int rowBase = blockIdx.y * BMG;
    int colBase = blockIdx.x * BNG;

    const __nv_bfloat16* Bp = Bm;
    const float* bp = bias;
    size_t dstOff = 0;
    if (EPI == 2) {
        int z = blockIdx.z;
        Bp = Bm + (size_t)z * DD2;
        dstOff = (size_t)z * (BB*KSEL*DD);
        bp = z ? bias2 : bias;
    }

    for (int i = tid; i < 16*BNG; i += 256)
        biasT[i] = bp[colBase + (i & (BNG-1))];
    __syncthreads();

    wmma::fragment<wmma::accumulator,16,16,16,float> acc[4][2];
    #pragma unroll
    for (int mi = 0; mi < 4; mi++)
        #pragma unroll
        for (int ni = 0; ni < 2; ni++)
            wmma::load_matrix_sync(acc[mi][ni], biasT + wn*32 + ni*16, BNG, wmma::mem_row_major);

    auto load_stage = [&](int s, int k0) {
        #pragma unroll
        for (int c = 0; c < 4; c++) {
            int lin = tid + c*256;
            int ar = lin >> 3, ac = (lin & 7)*8;
            unsigned da = (unsigned)__cvta_generic_to_shared(As + s*BMG*ALD + ar*ALD + ac);
            const void* ga = A + (size_t)(rowBase+ar)*K + k0 + ac;
            asm volatile("cp.async.cg.shared.global [%0], [%1], 16;\n" :: "r"(da), "l"(ga));
            int br = lin >> 4, bc = (lin & 15)*8;
            unsigned db = (unsigned)__cvta_generic_to_shared(Bs + s*BKG*BLD + br*BLD + bc);
            const void* gb = Bp + (size_t)(k0+br)*N + colBase + bc;
            asm volatile("cp.async.cg.shared.global [%0], [%1], 16;\n" :: "r"(db), "l"(gb));
        }
        asm volatile("cp.async.commit_group;\n");
    };

    int NK = K / BKG;
    load_stage(0, 0);
    load_stage(1, BKG);

    for (int i = 0; i < NK; i++) {
        asm volatile("cp.async.wait_group %0;\n" :: "n"(STG-2));
        __syncthreads();
        if (i + STG - 1 < NK) load_stage((i + STG - 1) % STG, (i + STG - 1) * BKG);
        else asm volatile("cp.async.commit_group;\n");
        int buf = i % STG;
        const __nv_bfloat16* Ab = As + buf*BMG*ALD + wm*64*ALD;
        const __nv_bfloat16* Bb = Bs + buf*BKG*BLD + wn*32;
        #pragma unroll
        for (int kk = 0; kk < BKG; kk += 16) {
            wmma::fragment<wmma::matrix_a,16,16,16,__nv_bfloat16,wmma::row_major> af[4];
            #pragma unroll
            for (int mi = 0; mi < 4; mi++)
                wmma::load_matrix_sync(af[mi], Ab + mi*16*ALD + kk, ALD);
            #pragma unroll
            for (int ni = 0; ni < 2; ni++) {
                wmma::fragment<wmma::matrix_b,16,16,16,__nv_bfloat16,wmma::row_major> bf;
                wmma::load_matrix_sync(bf, Bb + kk*BLD + ni*16, BLD);
                #pragma unroll
                for (int mi = 0; mi < 4; mi++)
                    wmma::mma_sync(acc[mi][ni], af[mi], bf, acc[mi][ni]);
            }
        }
    }

    // drain + stage C through smem
    asm volatile("cp.async.wait_group 0;\n");
    __syncthreads();
    float* Cs = (float*)smraw;   // 128 x 132
    #pragma unroll
    for (int mi = 0; mi < 4; mi++)
        #pragma unroll
        for (int ni = 0; ni < 2; ni++)
            wmma::store_matrix_sync(Cs + (wm*64 + mi*16)*132 + wn*32 + ni*16,
                                    acc[mi][ni], 132, wmma::mem_row_major);
    __syncthreads();

    if (EPI == 1) {
        float* C = (float*)Cout;
        float gate = 1.f / (1.f + __expf(-glp[0]));
        for (int c = tid; c < BMG*(BNG/4); c += 256) {
            int r = c >> 5, c4 = (c & 31)*4;
            size_t gi = (size_t)(rowBase + r)*N + colBase + c4;
            float4 hv = *(const float4*)(hres + gi);
            float4 cv = *(float4*)(Cs + r*132 + c4);
            float4 o;
            o.x = hv.x + gate*cv.x; o.y = hv.y + gate*cv.y;
            o.z = hv.z + gate*cv.z; o.w = hv.w + gate*cv.w;
            *(float4*)(C + gi) = o;
        }
    } else {
        __nv_bfloat16* C = (__nv_bfloat16*)Cout + dstOff;
        for (int c = tid; c < BMG*(BNG/8); c += 256) {
            int r = c >> 4, c8 = (c & 15)*8;
            const float* src = Cs + r*132 + c8;
            __nv_bfloat162 p0 = __float22bfloat162_rn(make_float2(src[0], src[1]));
            __nv_bfloat162 p1 = __float22bfloat162_rn(make_float2(src[2], src[3]));
            __nv_bfloat162 p2 = __float22bfloat162_rn(make_float2(src[4], src[5]));
            __nv_bfloat162 p3 = __float22bfloat162_rn(make_float2(src[6], src[7]));
            uint4 pk;
            pk.x = *(unsigned*)&p0; pk.y = *(unsigned*)&p1;
            pk.z = *(unsigned*)&p2; pk.w = *(unsigned*)&p3;
            *(uint4*)(C + (size_t)(rowBase + r)*N + colBase + c8) = pk;
        }
    }
}

// ---------------- tensor-core attention ----------------
// block: one (b,h), 128 t-rows. scores = Qs@Ks^T (wmma), softmax fp32, out = Ps@Vs (wmma).
#define QLD 72
#define SLD 72
#define SMEM_ATTN ((128*QLD + 64*QLD + 64*QLD)*2 + 128*SLD*4 + 128*QLD*2 + 64*4)

__global__ __launch_bounds__(256) void attn_kernel() {
    extern __shared__ char smc[];
    __nv_bfloat16* Qs = (__nv_bfloat16*)smc;        // 128 x QLD
    __nv_bfloat16* Ks = Qs + 128*QLD;               // 64 x QLD
    __nv_bfloat16* Vs = Ks + 64*QLD;                // 64 x QLD
    float* Ss = (float*)(Vs + 64*QLD);              // 128 x SLD (scores, reused as out)
    __nv_bfloat16* Ps = (__nv_bfloat16*)(Ss + 128*SLD);  // 128 x QLD
    float* colsum = (float*)(Ps + 128*QLD);         // 64

    int bh = blockIdx.x;
    int b = bh >> 4;
    int h = bh & 15;
    int t0 = blockIdx.y * 128;
    int tid = threadIdx.x;
    int warp = tid >> 5;

    if (tid < 64) colsum[tid] = 0.f;
    // load Q tile: 128 rows x 64 cols bf16 = 1024 16B chunks
    {
        const __nv_bfloat16* qsrc = g_qbf + (size_t)(b*TT + t0)*DD + h*DH;
        #pragma unroll
        for (int c = tid; c < 1024; c += 256) {
            int r = c >> 3, c8 = (c & 7)*8;
            *(uint4*)(Qs + r*QLD + c8) = *(const uint4*)(qsrc + (size_t)r*DD + c8);
        }
        const __nv_bfloat16* kbase = g_kvbf + (size_t)b*KSEL*DD + h*DH;
        const __nv_bfloat16* vbase = kbase + (size_t)BB*KSEL*DD;
        for (int c = tid; c < 512; c += 256) {
            int r = c >> 3, c8 = (c & 7)*8;
            *(uint4*)(Ks + r*QLD + c8) = *(const uint4*)(kbase + (size_t)r*DD + c8);
            *(uint4*)(Vs + r*QLD + c8) = *(const uint4*)(vbase + (size_t)r*DD + c8);
        }
    }
    __syncthreads();

    // scores: warp w -> rows [w*16, w*16+16), all 64 kk cols
    {
        wmma::fragment<wmma::accumulator,16,16,16,float> sc[4];
        #pragma unroll
        for (int n = 0; n < 4; n++) wmma::fill_fragment(sc[n], 0.f);
        #pragma unroll
        for (int k0 = 0; k0 < 64; k0 += 16) {
            wmma::fragment<wmma::matrix_a,16,16,16,__nv_bfloat16,wmma::row_major> af;
            wmma::load_matrix_sync(af, Qs + warp*16*QLD + k0, QLD);
            #pragma unroll
            for (int n = 0; n < 4; n++) {
                wmma::fragment<wmma::matrix_b,16,16,16,__nv_bfloat16,wmma::col_major> bf;
                wmma::load_matrix_sync(bf, Ks + n*16*QLD + k0, QLD);
                wmma::mma_sync(sc[n], af, bf, sc[n]);
            }
        }
        #pragma unroll
        for (int n = 0; n < 4; n++)
            wmma::store_matrix_sync(Ss + warp*16*SLD + n*16, sc[n], SLD, wmma::mem_row_major);
    }
    __syncthreads();

    // softmax: 2 threads per row, 32 cols each
    {
        int row = tid >> 1, half = tid & 1;
        const float* srow = Ss + row*SLD + half*32;
        float e[32]; float s = 0.f;
        #pragma unroll
        for (int j = 0; j < 32; j++) { e[j] = __expf(srow[j]*0.125f); s += e[j]; }
        float tot = s + __shfl_xor_sync(0xffffffffu, s, 1);
        float inv = 1.f / tot;
        __nv_bfloat162* prow = (__nv_bfloat162*)(Ps + row*QLD + half*32);
        #pragma unroll
        for (int j = 0; j < 16; j++)
            prow[j] = __float22bfloat162_rn(make_float2(e[2*j]*inv, e[2*j+1]*inv));
    }
    __syncthreads();

    // out = P@V (writes Ss region), and colsum of P
    {
        wmma::fragment<wmma::accumulator,16,16,16,float> oc[4];
        #pragma unroll
        for (int n = 0; n < 4; n++) wmma::fill_fragment(oc[n], 0.f);
        #pragma unroll
        for (int k0 = 0; k0 < 64; k0 += 16) {
            wmma::fragment<wmma::matrix_a,16,16,16,__nv_bfloat16,wmma::row_major> af;
            wmma::load_matrix_sync(af, Ps + warp*16*QLD + k0, QLD);
            #pragma unroll
            for (int n = 0; n < 4; n++) {
                wmma::fragment<wmma::matrix_b,16,16,16,__nv_bfloat16,wmma::row_major> bf;
                wmma::load_matrix_sync(bf, Vs + k0*QLD + n*16, QLD);
                wmma::mma_sync(oc[n], af, bf, oc[n]);
            }
        }
        #pragma unroll
        for (int n = 0; n < 4; n++)
            wmma::store_matrix_sync(Ss + warp*16*SLD + n*16, oc[n], SLD, wmma::mem_row_major);

        int c = tid & 63, seg = tid >> 6;
        float part = 0.f;
        for (int r = seg*32; r < seg*32 + 32; r++)
            part += __bfloat162float(Ps[r*QLD + c]);
        atomicAdd(&colsum[c], part);
    }
    __syncthreads();

    // write out bf16 + flush attnsum
    {
        int row = tid >> 1, half = tid & 1;
        const float* orow = Ss + row*SLD + half*32;
        __nv_bfloat16* dst = g_attnout + (size_t)(b*TT + t0 + row)*DD + h*DH + half*32;
        #pragma unroll
        for (int jj = 0; jj < 4; jj++) {
            const float* s8 = orow + jj*8;
            __nv_bfloat162 p0 = __float22bfloat162_rn(make_float2(s8[0], s8[1]));
            __nv_bfloat162 p1 = __float22bfloat162_rn(make_float2(s8[2], s8[3]));
            __nv_bfloat162 p2 = __float22bfloat162_rn(make_float2(s8[4], s8[5]));
            __nv_bfloat162 p3 = __float22bfloat162_rn(make_float2(s8[6], s8[7]));
            uint4 pk;
            pk.x = *(unsigned*)&p0; pk.y = *(unsigned*)&p1;
            pk.z = *(unsigned*)&p2; pk.w = *(unsigned*)&p3;
            *(uint4*)(dst + jj*8) = pk;
        }
        if (tid < 64) atomicAdd(&g_attnsum[b*KSEL + tid], colsum[tid]);
    }
}

// ---------------- scatter mean attention ----------------
__global__ void scatter_kernel(float* __restrict__ dout) {
    int i = threadIdx.x;
    if (i < BB*KSEL) {
        int b = i >> 6;
        dout[BTD + b*NN + g_topk[i]] = g_attnsum[i] * (1.f / (HH*TT));
    }
}

// ---------------- launch ----------------
extern "C" void kernel_launch(void* const* d_in, const int* in_sizes, int n_in,
                              void* d_out, int out_size) {
    const float* h    = (const float*)d_in[0];
    const float* mem  = (const float*)d_in[1];
    const float* act  = (const float*)d_in[2];
    const float* ln_g = (const float*)d_in[3];
    const float* ln_b = (const float*)d_in[4];
    const float* fw   = (const float*)d_in[5];
    const float* fb   = (const float*)d_in[6];
    const float* qw   = (const float*)d_in[7];
    const float* qb   = (const float*)d_in[8];
    const float* kw   = (const float*)d_in[9];
    const float* kb   = (const float*)d_in[10];
    const float* vw   = (const float*)d_in[11];
    const float* vb   = (const float*)d_in[12];
    const float* ow   = (const float*)d_in[13];
    const float* ob   = (const float*)d_in[14];
    const float* awp  = (const float*)d_in[15];
    const float* glp  = (const float*)d_in[16];
    float* dout = (float*)d_out;

    __nv_bfloat16 *wq;
    cudaGetSymbolAddress((void**)&wq, g_wbf);
    __nv_bfloat16 *wk = wq + DD2, *wo = wq + 3*DD2;
    __nv_bfloat16 *hnorm, *tkmem, *attnout, *qbf, *kvbf;
    cudaGetSymbolAddress((void**)&hnorm, g_hnorm);
    cudaGetSymbolAddress((void**)&tkmem, g_tkmem);
    cudaGetSymbolAddress((void**)&attnout, g_attnout);
    cudaGetSymbolAddress((void**)&qbf, g_qbf);
    cudaGetSymbolAddress((void**)&kvbf, g_kvbf);

    cudaFuncSetAttribute(gemm_bf16<0>, cudaFuncAttributeMaxDynamicSharedMemorySize, SMEM_GEMM);
    cudaFuncSetAttribute(gemm_bf16<1>, cudaFuncAttributeMaxDynamicSharedMemorySize, SMEM_GEMM);
    cudaFuncSetAttribute(gemm_bf16<2>, cudaFuncAttributeMaxDynamicSharedMemorySize, SMEM_GEMM);
    cudaFuncSetAttribute(attn_kernel, cudaFuncAttributeMaxDynamicSharedMemorySize, SMEM_ATTN);

    zero_kernel<<<(BB*NN + 255)/256, 256>>>(dout);
    convw_kernel<<<2048, 256>>>(qw, kw, vw, ow);
    ln_kernel<<<BT, 256>>>(h, ln_g, ln_b);

    // q-gemm placed in the profiled launch slot
    gemm_bf16<0><<<dim3(DD/BNG, BT/BMG), 256, SMEM_GEMM>>>(
        hnorm, wq, qb, nullptr, qbf, nullptr, nullptr, BT, DD, DD);

    hsum_kernel<<<dim3(BB, 4, 16), 256>>>(h);
    focus_kernel<<<dim3(BB, 8), 256>>>(fw, fb, ln_g, ln_b);
    sel_kernel<<<NN/8, 256>>>(mem, act, awp);
    topk_kernel<<<BB, 1024>>>();
    gather_kernel<<<BB*KSEL, 256>>>(mem);

    gemm_bf16<2><<<dim3(DD/BNG, (BB*KSEL)/BMG, 2), 256, SMEM_GEMM>>>(
        tkmem, wk, kb, vb, kvbf, nullptr, nullptr, BB*KSEL, DD, DD);

    attn_kernel<<<dim3(BB*HH, TT/128), 256, SMEM_ATTN>>>();

    gemm_bf16<1><<<dim3(DD/BNG, BT/BMG), 256, SMEM_GEMM>>>(
        attnout, wo, ob, nullptr, dout, h, glp, BT, DD, DD);

    scatter_kernel<<<1, 512>>>(dout);
}